// round 14
// baseline (speedup 1.0000x reference)
#include <cuda_runtime.h>
#include <cuda_fp16.h>
#include <math.h>
#include <stdint.h>

#define BATCH 8
#define SEQ   2048
#define DIM   512
#define M_TOT (BATCH * SEQ)   // 16384
#define NCAT  (3 * DIM)       // 1536

// Scratch (device globals)
__device__ float  g_sig [M_TOT * DIM];                 // sigmoid(q) f32
__device__ float  g_kw  [M_TOT * DIM];                 // exp(k) f32 [i][d]
__device__ float  g_v   [M_TOT * DIM];                 // v f32 [i][d]
__device__ __half g_xh  [M_TOT * DIM];                 // fp16(x) [m][k]
__device__ __half g_wh  [NCAT * DIM];                  // fp16 W concat [n][k]
__device__ __half g_dwh [(size_t)BATCH * SEQ * SEQ];   // fp16(exp(coef*dis)) [b][j][i]
__device__ __half g_kwh [(size_t)BATCH * DIM * SEQ];   // fp16(kw)    [b][d][i]
__device__ __half g_kwvh[(size_t)BATCH * DIM * SEQ];   // fp16(kw*v)  [b][d][i]

// ---------------------------------------------------------------------------
// helpers
// ---------------------------------------------------------------------------
__device__ __forceinline__ uint32_t smem_u32(const void* p) {
    uint32_t a;
    asm("{ .reg .u64 t; cvta.to.shared.u64 t, %1; cvt.u32.u64 %0, t; }" : "=r"(a) : "l"(p));
    return a;
}

#define CP_ASYNC16(dst, src) \
    asm volatile("cp.async.cg.shared.global [%0], [%1], 16;" :: "r"(dst), "l"(src))
#define CP_COMMIT() asm volatile("cp.async.commit_group;" ::: "memory")
#define CP_WAIT(n)  asm volatile("cp.async.wait_group %0;" :: "n"(n) : "memory")

// fp16 m16n8k16
__device__ __forceinline__ void mma16(float* c, const uint32_t* a, const uint32_t* b) {
    asm volatile(
        "mma.sync.aligned.m16n8k16.row.col.f32.f16.f16.f32 "
        "{%0,%1,%2,%3},{%4,%5,%6,%7},{%8,%9},{%0,%1,%2,%3};"
        : "+f"(c[0]), "+f"(c[1]), "+f"(c[2]), "+f"(c[3])
        : "r"(a[0]), "r"(a[1]), "r"(a[2]), "r"(a[3]), "r"(b[0]), "r"(b[1]));
}

__device__ __forceinline__ void ldsm_x4(uint32_t* r, uint32_t addr) {
    asm volatile("ldmatrix.sync.aligned.m8n8.x4.shared.b16 {%0,%1,%2,%3}, [%4];"
        : "=r"(r[0]), "=r"(r[1]), "=r"(r[2]), "=r"(r[3]) : "r"(addr));
}

// ---------------------------------------------------------------------------
// Weight convert+concat (NO transpose): g_wh[z*512 + n][k] = fp16(W_z[n][k])
// ---------------------------------------------------------------------------
__global__ void wconv_kernel(const float* __restrict__ Wq,
                             const float* __restrict__ Wk,
                             const float* __restrict__ Wv) {
    const float* W = (blockIdx.y == 0) ? Wq : (blockIdx.y == 1) ? Wk : Wv;
    int i = (blockIdx.x * 256 + threadIdx.x) * 4;
    float4 v = *(const float4*)&W[i];
    __half* dst = g_wh + (size_t)blockIdx.y * DIM * DIM + i;
    *(__half2*)&dst[0] = __floats2half2_rn(v.x, v.y);
    *(__half2*)&dst[2] = __floats2half2_rn(v.z, v.w);
}

// ---------------------------------------------------------------------------
// x convert: g_xh = fp16(x)
// ---------------------------------------------------------------------------
__global__ void xh_kernel(const float* __restrict__ x) {
    size_t i = ((size_t)blockIdx.x * blockDim.x + threadIdx.x) * 4;
    float4 v = *(const float4*)(x + i);
    *(__half2*)&g_xh[i]     = __floats2half2_rn(v.x, v.y);
    *(__half2*)&g_xh[i + 2] = __floats2half2_rn(v.z, v.w);
}

// ---------------------------------------------------------------------------
// dwt: g_dwh[b][j][i] = fp16(exp(coef * dis[b][i][j]))  (transpose + exp)
// ---------------------------------------------------------------------------
__global__ void dwt_kernel(const float* __restrict__ dis,
                           const float* __restrict__ alpha_p) {
    __shared__ float tile[32][33];
    const float coef = -(alpha_p[0] * 11.0f);   // -alpha*log2(2048)
    const float* db = dis + (size_t)blockIdx.z * SEQ * SEQ;
    __half* ob = g_dwh + (size_t)blockIdx.z * SEQ * SEQ;
    int j = blockIdx.x * 32 + threadIdx.x;
    int i = blockIdx.y * 32 + threadIdx.y;
    #pragma unroll
    for (int r = 0; r < 32; r += 8)
        tile[threadIdx.y + r][threadIdx.x] = __expf(coef * db[(size_t)(i + r) * SEQ + j]);
    __syncthreads();
    int io = blockIdx.y * 32 + threadIdx.x;
    int jo = blockIdx.x * 32 + threadIdx.y;
    #pragma unroll
    for (int r = 0; r < 32; r += 8)
        ob[(size_t)(jo + r) * SEQ + io] = __float2half_rn(tile[threadIdx.x][threadIdx.y + r]);
}

// ---------------------------------------------------------------------------
// kvt: g_kwh[b][d][i] = fp16(kw); g_kwvh[b][d][i] = fp16(kw*v)  (transpose)
// ---------------------------------------------------------------------------
__global__ void kvt_kernel() {
    __shared__ float t1[32][33];
    __shared__ float t2[32][33];
    const float* kwb = g_kw + (size_t)blockIdx.z * SEQ * DIM;
    const float* vb  = g_v  + (size_t)blockIdx.z * SEQ * DIM;
    __half* o1 = g_kwvh + (size_t)blockIdx.z * DIM * SEQ;
    __half* o2 = g_kwh  + (size_t)blockIdx.z * DIM * SEQ;
    int d = blockIdx.x * 32 + threadIdx.x;
    int i = blockIdx.y * 32 + threadIdx.y;
    #pragma unroll
    for (int r = 0; r < 32; r += 8) {
        float kw = kwb[(size_t)(i + r) * DIM + d];
        float vv = vb [(size_t)(i + r) * DIM + d];
        t2[threadIdx.y + r][threadIdx.x] = kw;
        t1[threadIdx.y + r][threadIdx.x] = kw * vv;
    }
    __syncthreads();
    int io = blockIdx.y * 32 + threadIdx.x;
    int do_ = blockIdx.x * 32 + threadIdx.y;
    #pragma unroll
    for (int r = 0; r < 32; r += 8) {
        o1[(size_t)(do_ + r) * SEQ + io] = __float2half_rn(t1[threadIdx.x][threadIdx.y + r]);
        o2[(size_t)(do_ + r) * SEQ + io] = __float2half_rn(t2[threadIdx.x][threadIdx.y + r]);
    }
}

// ---------------------------------------------------------------------------
// QKV GEMM (fp16 m16n8k16 + ldmatrix): C[m,n] = sum_k xh[m,k] * wh[n,k]
// BM=256, BN=128, BK=32, 256 thr (8 warps 4x2), warp tile 64x64,
// 4-stage cp.async, 1 sync/tile. grid (12, 64), 1 CTA/SM.
// ---------------------------------------------------------------------------
#define QASTH 40                           // halves per row (32 + 8 pad)
#define QA_BYTES (256 * QASTH * 2)         // 20480
#define QB_BYTES (128 * QASTH * 2)         // 10240
#define QSTG_BYTES (QA_BYTES + QB_BYTES)   // 30720
#define QKV_SMEM (4 * QSTG_BYTES)          // 122880
#define QN_KTILE (DIM / 32)                // 16

__global__ void __launch_bounds__(256, 1)
qkv_kernel() {
    extern __shared__ char smc[];
    const uint32_t sb = smem_u32(smc);
    const int t = threadIdx.x, l = t & 31, w = t >> 5;
    const int wm = w >> 1, wn = w & 1;     // 4 x 2 warp grid
    const int m0 = blockIdx.y * 256, n0 = blockIdx.x * 128;

    float acc[4][8][4] = {};

    // ldmatrix geometry (byte offsets within a stage)
    const uint32_t aRow = wm * 64 + (l & 15);                 // + mt*16
    const uint32_t aCol = 8 * (l >> 4);                       // + kk
    const uint32_t bRow = wn * 64 + 8 * (l >> 4) + (l & 7);   // + np*16
    const uint32_t bCol = 8 * ((l >> 3) & 1);                 // + kk
    const uint32_t aOff = (aRow * QASTH + aCol) * 2;
    const uint32_t bOff = QA_BYTES + (bRow * QASTH + bCol) * 2;

    auto load_stage = [&](int kt, int stage) {
        const int k0 = kt * 32;
        const uint32_t s0 = sb + stage * QSTG_BYTES;
        // A: 256 rows x 32 k halves; thread t owns row t, 4 chunks of 16B
        const __half* srcA = g_xh + (size_t)(m0 + t) * DIM + k0;
        const uint32_t aBase = s0 + t * (QASTH * 2);
        #pragma unroll
        for (int ch = 0; ch < 4; ch++)
            CP_ASYNC16(aBase + ch * 16, srcA + ch * 8);
        // B: 128 rows; 2 threads/row, 2 chunks each
        const int br = t >> 1, bc = 2 * (t & 1);
        const __half* srcB = g_wh + (size_t)(n0 + br) * DIM + k0;
        const uint32_t bBase = s0 + QA_BYTES + br * (QASTH * 2);
        CP_ASYNC16(bBase + bc * 16,       srcB + bc * 8);
        CP_ASYNC16(bBase + (bc + 1) * 16, srcB + (bc + 1) * 8);
        CP_COMMIT();
    };

    auto compute_stage = [&](int stage) {
        const uint32_t s0 = sb + stage * QSTG_BYTES;
        #pragma unroll
        for (int ks = 0; ks < 2; ks++) {
            const int kk = ks * 16;
            uint32_t a[4][4], b[8][2];
            #pragma unroll
            for (int mt = 0; mt < 4; mt++)
                ldsm_x4(a[mt], s0 + aOff + (mt * 16 * QASTH + kk) * 2);
            #pragma unroll
            for (int np = 0; np < 4; np++) {
                uint32_t r[4];
                ldsm_x4(r, s0 + bOff + (np * 16 * QASTH + kk) * 2);
                b[np * 2][0] = r[0]; b[np * 2][1] = r[1];
                b[np * 2 + 1][0] = r[2]; b[np * 2 + 1][1] = r[3];
            }
            #pragma unroll
            for (int mt = 0; mt < 4; mt++)
                #pragma unroll
                for (int nt = 0; nt < 8; nt++)
                    mma16(acc[mt][nt], a[mt], b[nt]);
        }
    };

    load_stage(0, 0);
    load_stage(1, 1);
    load_stage(2, 2);
    for (int kt = 0; kt < QN_KTILE; kt++) {
        if (kt == QN_KTILE - 1) { CP_WAIT(0); } else { CP_WAIT(2); }
        __syncthreads();
        compute_stage(kt & 3);
        if (kt + 3 < QN_KTILE) load_stage(kt + 3, (kt + 3) & 3);
    }

    // epilogue by n-segment
    const int type = n0 >> 9;                 // 0:q 1:k 2:v (BN=128 divides 512)
    float* dst = (type == 0) ? g_sig : (type == 1) ? g_kw : g_v;
    const int nl0 = n0 - type * 512;

    #pragma unroll
    for (int mt = 0; mt < 4; mt++) {
        #pragma unroll
        for (int nt = 0; nt < 8; nt++) {
            int row = m0 + wm * 64 + mt * 16 + (l >> 2);
            int col = nl0 + wn * 64 + nt * 8 + 2 * (l & 3);
            float c0 = acc[mt][nt][0], c1 = acc[mt][nt][1];
            float c2 = acc[mt][nt][2], c3 = acc[mt][nt][3];
            if (type == 0) {
                c0 = 1.0f / (1.0f + __expf(-c0));
                c1 = 1.0f / (1.0f + __expf(-c1));
                c2 = 1.0f / (1.0f + __expf(-c2));
                c3 = 1.0f / (1.0f + __expf(-c3));
            } else if (type == 1) {
                c0 = __expf(c0); c1 = __expf(c1);
                c2 = __expf(c2); c3 = __expf(c3);
            }
            *(float2*)&dst[(size_t)row * DIM + col]       = make_float2(c0, c1);
            *(float2*)&dst[(size_t)(row + 8) * DIM + col] = make_float2(c2, c3);
        }
    }
}

// ---------------------------------------------------------------------------
// Attention dual-GEMM (fp16 m16n8k16 + ldmatrix, 4-stage, 1 sync/tile)
// BM=256 (j), BN=64 (d), BK=32 (i); 256 thr (8 warps 4x2), warp tile 64x32
// dual acc. grid (8, 8, 8), 1 CTA/SM.
// ---------------------------------------------------------------------------
#define ASTH 40
#define AA_BYTES (256 * ASTH * 2)          // 20480
#define AB_BYTES (64 * ASTH * 2)           // 5120
#define ASTG_BYTES (AA_BYTES + 2 * AB_BYTES)   // 30720
#define ATTN_SMEM (4 * ASTG_BYTES)         // 122880
#define N_ITILE (SEQ / 32)                 // 64

__global__ void __launch_bounds__(256, 1)
attn_kernel(float* __restrict__ out) {
    extern __shared__ char smc[];
    const uint32_t sb = smem_u32(smc);
    const int t = threadIdx.x, l = t & 31, w = t >> 5;
    const int wm = w >> 1, wn = w & 1;     // 4 x 2
    const int b = blockIdx.z, j0 = blockIdx.y * 256, d0 = blockIdx.x * 64;

    const __half* dwb = g_dwh  + (size_t)b * SEQ * SEQ;   // [j][i]
    const __half* kvb = g_kwvh + (size_t)b * DIM * SEQ;   // [d][i]
    const __half* kwb = g_kwh  + (size_t)b * DIM * SEQ;   // [d][i]

    const __half* srcA  = dwb + (size_t)(j0 + t) * SEQ;          // row j0+t
    const __half* srcB1 = kvb + (size_t)(d0 + (t >> 2)) * SEQ;   // row d0+(t>>2)
    const __half* srcB2 = kwb + (size_t)(d0 + (t >> 2)) * SEQ;

    float acc1[4][4][4] = {};
    float acc2[4][4][4] = {};

    // ldmatrix geometry
    const uint32_t aRow = wm * 64 + (l & 15);
    const uint32_t aCol = 8 * (l >> 4);
    const uint32_t bRow = wn * 32 + 8 * (l >> 4) + (l & 7);
    const uint32_t bCol = 8 * ((l >> 3) & 1);
    const uint32_t aOff  = (aRow * ASTH + aCol) * 2;
    const uint32_t b1Off = AA_BYTES + (bRow * ASTH + bCol) * 2;
    const uint32_t b2Off = b1Off + AB_BYTES;

    auto load_stage = [&](int tile, int stage) {
        const int i0 = tile * 32;
        const uint32_t s0 = sb + stage * ASTG_BYTES;
        // A: 256 rows; thread t owns row t, 4 chunks
        const uint32_t aBase = s0 + t * (ASTH * 2);
        #pragma unroll
        for (int ch = 0; ch < 4; ch++)
            CP_ASYNC16(aBase + ch * 16, srcA + i0 + ch * 8);
        // B1/B2: 64 rows; 4 threads/row, 1 chunk each per array
        const int bc = t & 3;
        const uint32_t b1Base = s0 + AA_BYTES + (t >> 2) * (ASTH * 2);
        const uint32_t b2Base = b1Base + AB_BYTES;
        CP_ASYNC16(b1Base + bc * 16, srcB1 + i0 + bc * 8);
        CP_ASYNC16(b2Base + bc * 16, srcB2 + i0 + bc * 8);
        CP_COMMIT();
    };

    auto compute_stage = [&](int stage) {
        const uint32_t s0 = sb + stage * ASTG_BYTES;
        #pragma unroll
        for (int ks = 0; ks < 2; ks++) {
            const int kk = ks * 16;
            uint32_t a[4][4], b1[4][2], b2[4][2];
            #pragma unroll
            for (int mt = 0; mt < 4; mt++)
                ldsm_x4(a[mt], s0 + aOff + (mt * 16 * ASTH + kk) * 2);
            #pragma unroll
            for (int np = 0; np < 2; np++) {
                uint32_t r[4];
                ldsm_x4(r, s0 + b1Off + (np * 16 * ASTH + kk) * 2);
                b1[np * 2][0] = r[0]; b1[np * 2][1] = r[1];
                b1[np * 2 + 1][0] = r[2]; b1[np * 2 + 1][1] = r[3];
                ldsm_x4(r, s0 + b2Off + (np * 16 * ASTH + kk) * 2);
                b2[np * 2][0] = r[0]; b2[np * 2][1] = r[1];
                b2[np * 2 + 1][0] = r[2]; b2[np * 2 + 1][1] = r[3];
            }
            #pragma unroll
            for (int mt = 0; mt < 4; mt++) {
                #pragma unroll
                for (int nt = 0; nt < 4; nt++) {
                    mma16(acc1[mt][nt], a[mt], b1[nt]);
                    mma16(acc2[mt][nt], a[mt], b2[nt]);
                }
            }
        }
    };

    load_stage(0, 0);
    load_stage(1, 1);
    load_stage(2, 2);
    for (int tile = 0; tile < N_ITILE; tile++) {
        if (tile == N_ITILE - 1) { CP_WAIT(0); } else { CP_WAIT(2); }
        __syncthreads();
        compute_stage(tile & 3);
        if (tile + 3 < N_ITILE) load_stage(tile + 3, (tile + 3) & 3);
    }

    // epilogue: out = sig * acc1/acc2
    const float* sigb = g_sig + (size_t)b * SEQ * DIM;
    float* outb = out + (size_t)b * SEQ * DIM;
    #pragma unroll
    for (int mt = 0; mt < 4; mt++) {
        #pragma unroll
        for (int nt = 0; nt < 4; nt++) {
            int jr = j0 + wm * 64 + mt * 16 + (l >> 2);
            int dc = d0 + wn * 32 + nt * 8 + 2 * (l & 3);
            size_t i0x = (size_t)jr * DIM + dc;
            size_t i1x = (size_t)(jr + 8) * DIM + dc;
            float2 s0 = *(const float2*)&sigb[i0x];
            float2 s1 = *(const float2*)&sigb[i1x];
            float2 o0, o1;
            o0.x = s0.x * __fdividef(acc1[mt][nt][0], acc2[mt][nt][0]);
            o0.y = s0.y * __fdividef(acc1[mt][nt][1], acc2[mt][nt][1]);
            o1.x = s1.x * __fdividef(acc1[mt][nt][2], acc2[mt][nt][2]);
            o1.y = s1.y * __fdividef(acc1[mt][nt][3], acc2[mt][nt][3]);
            *(float2*)&outb[i0x] = o0;
            *(float2*)&outb[i1x] = o1;
        }
    }
}

// ---------------------------------------------------------------------------
// Launch
// ---------------------------------------------------------------------------
extern "C" void kernel_launch(void* const* d_in, const int* in_sizes, int n_in,
                              void* d_out, int out_size) {
    const float* x     = (const float*)d_in[0];
    const float* dis   = (const float*)d_in[1];
    const float* Wq    = (const float*)d_in[2];
    const float* Wk    = (const float*)d_in[3];
    const float* Wv    = (const float*)d_in[4];
    const float* alpha = (const float*)d_in[5];
    float* out = (float*)d_out;

    cudaFuncSetAttribute(attn_kernel, cudaFuncAttributeMaxDynamicSharedMemorySize, ATTN_SMEM);
    cudaFuncSetAttribute(qkv_kernel,  cudaFuncAttributeMaxDynamicSharedMemorySize, QKV_SMEM);

    {   // weight convert+concat (fp16, [n][k])
        dim3 grid(256, 3), block(256);
        wconv_kernel<<<grid, block>>>(Wq, Wk, Wv);
    }
    {   // x convert
        xh_kernel<<<8192, 256>>>(x);
    }
    {   // dw = fp16(exp(coef*dis)) transposed [b][j][i]
        dim3 grid(SEQ / 32, SEQ / 32, BATCH), block(32, 8);
        dwt_kernel<<<grid, block>>>(dis, alpha);
    }
    {   // fp16 QKV projection (BM=256, BN=128)
        dim3 grid(NCAT / 128, M_TOT / 256), block(256);
        qkv_kernel<<<grid, block, QKV_SMEM>>>();
    }
    {   // kw / kw*v transpose to fp16 [b][d][i]
        dim3 grid(DIM / 32, SEQ / 32, BATCH), block(32, 8);
        kvt_kernel<<<grid, block>>>();
    }
    {   // fp16 dual-GEMM attention (BM=256, BN=64)
        dim3 grid(DIM / 64, SEQ / 256, BATCH), block(256);
        attn_kernel<<<grid, block, ATTN_SMEM>>>(out);
    }
}

// round 15
// speedup vs baseline: 1.1074x; 1.1074x over previous
#include <cuda_runtime.h>
#include <cuda_fp16.h>
#include <math.h>
#include <stdint.h>

#define BATCH 8
#define SEQ   2048
#define DIM   512
#define M_TOT (BATCH * SEQ)   // 16384
#define NCAT  (3 * DIM)       // 1536

// Scratch (device globals)
__device__ float  g_sig [M_TOT * DIM];                 // sigmoid(q) f32
__device__ float  g_kw  [M_TOT * DIM];                 // exp(k) f32 [i][d]
__device__ float  g_v   [M_TOT * DIM];                 // v f32 [i][d]
__device__ __half g_xh  [M_TOT * DIM];                 // fp16(x) [m][k]
__device__ __half g_wh  [NCAT * DIM];                  // fp16 W concat [n][k]
__device__ __half g_dwh [(size_t)BATCH * SEQ * SEQ];   // fp16(exp(coef*dis)) [b][j][i]
__device__ __half g_kwh [(size_t)BATCH * DIM * SEQ];   // fp16(kw)    [b][d][i]
__device__ __half g_kwvh[(size_t)BATCH * DIM * SEQ];   // fp16(kw*v)  [b][d][i]

// ---------------------------------------------------------------------------
// helpers
// ---------------------------------------------------------------------------
__device__ __forceinline__ uint32_t smem_u32(const void* p) {
    uint32_t a;
    asm("{ .reg .u64 t; cvta.to.shared.u64 t, %1; cvt.u32.u64 %0, t; }" : "=r"(a) : "l"(p));
    return a;
}

#define CP_ASYNC16(dst, src) \
    asm volatile("cp.async.cg.shared.global [%0], [%1], 16;" :: "r"(dst), "l"(src))
#define CP_COMMIT() asm volatile("cp.async.commit_group;" ::: "memory")
#define CP_WAIT(n)  asm volatile("cp.async.wait_group %0;" :: "n"(n) : "memory")

// fp16 m16n8k16
__device__ __forceinline__ void mma16(float* c, const uint32_t* a, const uint32_t* b) {
    asm volatile(
        "mma.sync.aligned.m16n8k16.row.col.f32.f16.f16.f32 "
        "{%0,%1,%2,%3},{%4,%5,%6,%7},{%8,%9},{%0,%1,%2,%3};"
        : "+f"(c[0]), "+f"(c[1]), "+f"(c[2]), "+f"(c[3])
        : "r"(a[0]), "r"(a[1]), "r"(a[2]), "r"(a[3]), "r"(b[0]), "r"(b[1]));
}

__device__ __forceinline__ void ldsm_x4(uint32_t* r, uint32_t addr) {
    asm volatile("ldmatrix.sync.aligned.m8n8.x4.shared.b16 {%0,%1,%2,%3}, [%4];"
        : "=r"(r[0]), "=r"(r[1]), "=r"(r[2]), "=r"(r[3]) : "r"(addr));
}

// ---------------------------------------------------------------------------
// Weight convert+concat (NO transpose): g_wh[z*512 + n][k] = fp16(W_z[n][k])
// ---------------------------------------------------------------------------
__global__ void wconv_kernel(const float* __restrict__ Wq,
                             const float* __restrict__ Wk,
                             const float* __restrict__ Wv) {
    const float* W = (blockIdx.y == 0) ? Wq : (blockIdx.y == 1) ? Wk : Wv;
    int i = (blockIdx.x * 256 + threadIdx.x) * 4;
    float4 v = *(const float4*)&W[i];
    __half* dst = g_wh + (size_t)blockIdx.y * DIM * DIM + i;
    *(__half2*)&dst[0] = __floats2half2_rn(v.x, v.y);
    *(__half2*)&dst[2] = __floats2half2_rn(v.z, v.w);
}

// ---------------------------------------------------------------------------
// x convert: g_xh = fp16(x)
// ---------------------------------------------------------------------------
__global__ void xh_kernel(const float* __restrict__ x) {
    size_t i = ((size_t)blockIdx.x * blockDim.x + threadIdx.x) * 4;
    float4 v = *(const float4*)(x + i);
    *(__half2*)&g_xh[i]     = __floats2half2_rn(v.x, v.y);
    *(__half2*)&g_xh[i + 2] = __floats2half2_rn(v.z, v.w);
}

// ---------------------------------------------------------------------------
// dwt v2: g_dwh[b][j][i] = fp16(exp(coef*dis[b][i][j]))
// 64(i) x 32(j) tiles, block (32,8); f32 coalesced loads, half2 128B stores.
// smem tile [j][i] halves, row stride 66 (33 words -> conflict-free).
// grid (SEQ/32, SEQ/64, 8)
// ---------------------------------------------------------------------------
__global__ void dwt_kernel(const float* __restrict__ dis,
                           const float* __restrict__ alpha_p) {
    __shared__ __half tile[32][66];
    const float coef = -(alpha_p[0] * 11.0f);   // -alpha*log2(2048)
    const float* db = dis + (size_t)blockIdx.z * SEQ * SEQ;
    __half* ob = g_dwh + (size_t)blockIdx.z * SEQ * SEQ;
    const int j0 = blockIdx.x * 32, i0 = blockIdx.y * 64;
    const int x = threadIdx.x, y = threadIdx.y;

    #pragma unroll
    for (int r = 0; r < 8; r++) {
        int i = r * 8 + y;
        float v = db[(size_t)(i0 + i) * SEQ + j0 + x];
        tile[x][i] = __float2half_rn(__expf(coef * v));
    }
    __syncthreads();
    #pragma unroll
    for (int s = 0; s < 4; s++) {
        int j = s * 8 + y;
        *(__half2*)&ob[(size_t)(j0 + j) * SEQ + i0 + 2 * x] = *(__half2*)&tile[j][2 * x];
    }
}

// ---------------------------------------------------------------------------
// kvt v2: g_kwh[b][d][i] = fp16(kw); g_kwvh[b][d][i] = fp16(kw*v)
// 64(i) x 32(d) tiles, block (32,8); half2 128B stores.
// grid (DIM/32, SEQ/64, 8)
// ---------------------------------------------------------------------------
__global__ void kvt_kernel() {
    __shared__ __half t1[32][66];   // kw*v
    __shared__ __half t2[32][66];   // kw
    const float* kwb = g_kw + (size_t)blockIdx.z * SEQ * DIM;
    const float* vb  = g_v  + (size_t)blockIdx.z * SEQ * DIM;
    __half* o1 = g_kwvh + (size_t)blockIdx.z * DIM * SEQ;
    __half* o2 = g_kwh  + (size_t)blockIdx.z * DIM * SEQ;
    const int d0 = blockIdx.x * 32, i0 = blockIdx.y * 64;
    const int x = threadIdx.x, y = threadIdx.y;

    #pragma unroll
    for (int r = 0; r < 8; r++) {
        int i = r * 8 + y;
        float kw = kwb[(size_t)(i0 + i) * DIM + d0 + x];
        float vv = vb [(size_t)(i0 + i) * DIM + d0 + x];
        t2[x][i] = __float2half_rn(kw);
        t1[x][i] = __float2half_rn(kw * vv);
    }
    __syncthreads();
    #pragma unroll
    for (int s = 0; s < 4; s++) {
        int d = s * 8 + y;
        *(__half2*)&o1[(size_t)(d0 + d) * SEQ + i0 + 2 * x] = *(__half2*)&t1[d][2 * x];
        *(__half2*)&o2[(size_t)(d0 + d) * SEQ + i0 + 2 * x] = *(__half2*)&t2[d][2 * x];
    }
}

// ---------------------------------------------------------------------------
// QKV GEMM (fp16 m16n8k16 + ldmatrix): C[m,n] = sum_k xh[m,k] * wh[n,k]
// BM=128, BN=128, BK=32, 128 thr (4 warps 2x2), warp tile 64x64,
// 3-stage cp.async, 1 sync/tile. grid (12, 128), 3 CTAs/SM.  (R13 config)
// ---------------------------------------------------------------------------
#define QASTH 40                           // halves per row (32 + 8 pad)
#define QA_BYTES (128 * QASTH * 2)         // 10240
#define QSTG_BYTES (2 * QA_BYTES)          // 20480
#define QKV_SMEM (3 * QSTG_BYTES)          // 61440
#define QN_KTILE (DIM / 32)                // 16

__global__ void __launch_bounds__(128, 3)
qkv_kernel() {
    extern __shared__ char smc[];
    const uint32_t sb = smem_u32(smc);
    const int t = threadIdx.x, l = t & 31, w = t >> 5;
    const int wm = w >> 1, wn = w & 1;
    const int m0 = blockIdx.y * 128, n0 = blockIdx.x * 128;

    float acc[4][8][4] = {};

    const uint32_t aRow = wm * 64 + (l & 15);
    const uint32_t aCol = 8 * (l >> 4);
    const uint32_t bRow = wn * 64 + 8 * (l >> 4) + (l & 7);
    const uint32_t bCol = 8 * ((l >> 3) & 1);
    const uint32_t aOff = (aRow * QASTH + aCol) * 2;
    const uint32_t bOff = QA_BYTES + (bRow * QASTH + bCol) * 2;

    auto load_stage = [&](int kt, int stage) {
        const int k0 = kt * 32;
        const uint32_t s0 = sb + stage * QSTG_BYTES;
        const __half* srcA = g_xh + (size_t)(m0 + t) * DIM + k0;
        const uint32_t aBase = s0 + t * (QASTH * 2);
        #pragma unroll
        for (int ch = 0; ch < 4; ch++)
            CP_ASYNC16(aBase + ch * 16, srcA + ch * 8);
        const __half* srcB = g_wh + (size_t)(n0 + t) * DIM + k0;
        const uint32_t bBase = s0 + QA_BYTES + t * (QASTH * 2);
        #pragma unroll
        for (int ch = 0; ch < 4; ch++)
            CP_ASYNC16(bBase + ch * 16, srcB + ch * 8);
        CP_COMMIT();
    };

    auto compute_stage = [&](int stage) {
        const uint32_t s0 = sb + stage * QSTG_BYTES;
        #pragma unroll
        for (int ks = 0; ks < 2; ks++) {
            const int kk = ks * 16;
            uint32_t a[4][4], b[8][2];
            #pragma unroll
            for (int mt = 0; mt < 4; mt++)
                ldsm_x4(a[mt], s0 + aOff + (mt * 16 * QASTH + kk) * 2);
            #pragma unroll
            for (int np = 0; np < 4; np++) {
                uint32_t r[4];
                ldsm_x4(r, s0 + bOff + (np * 16 * QASTH + kk) * 2);
                b[np * 2][0] = r[0]; b[np * 2][1] = r[1];
                b[np * 2 + 1][0] = r[2]; b[np * 2 + 1][1] = r[3];
            }
            #pragma unroll
            for (int mt = 0; mt < 4; mt++)
                #pragma unroll
                for (int nt = 0; nt < 8; nt++)
                    mma16(acc[mt][nt], a[mt], b[nt]);
        }
    };

    load_stage(0, 0);
    load_stage(1, 1);
    for (int kt = 0; kt < QN_KTILE; kt++) {
        if (kt == QN_KTILE - 1) { CP_WAIT(0); } else { CP_WAIT(1); }
        __syncthreads();
        compute_stage(kt % 3);
        if (kt + 2 < QN_KTILE) load_stage(kt + 2, (kt + 2) % 3);
    }

    const int type = n0 >> 9;
    float* dst = (type == 0) ? g_sig : (type == 1) ? g_kw : g_v;
    const int nl0 = n0 - type * 512;

    #pragma unroll
    for (int mt = 0; mt < 4; mt++) {
        #pragma unroll
        for (int nt = 0; nt < 8; nt++) {
            int row = m0 + wm * 64 + mt * 16 + (l >> 2);
            int col = nl0 + wn * 64 + nt * 8 + 2 * (l & 3);
            float c0 = acc[mt][nt][0], c1 = acc[mt][nt][1];
            float c2 = acc[mt][nt][2], c3 = acc[mt][nt][3];
            if (type == 0) {
                c0 = 1.0f / (1.0f + __expf(-c0));
                c1 = 1.0f / (1.0f + __expf(-c1));
                c2 = 1.0f / (1.0f + __expf(-c2));
                c3 = 1.0f / (1.0f + __expf(-c3));
            } else if (type == 1) {
                c0 = __expf(c0); c1 = __expf(c1);
                c2 = __expf(c2); c3 = __expf(c3);
            }
            *(float2*)&dst[(size_t)row * DIM + col]       = make_float2(c0, c1);
            *(float2*)&dst[(size_t)(row + 8) * DIM + col] = make_float2(c2, c3);
        }
    }
}

// ---------------------------------------------------------------------------
// Attention dual-GEMM (fp16 m16n8k16 + ldmatrix, 3-stage, 1 sync/tile)
// BM=128 (j), BN=64 (d), BK=32 (i); 128 thr (4 warps 2x2), warp tile 64x32
// dual acc. grid (8, 16, 8), 3 CTAs/SM.  (R13 config)
// ---------------------------------------------------------------------------
#define ASTH 40
#define AA_BYTES (128 * ASTH * 2)          // 10240
#define AB_BYTES (64 * ASTH * 2)           // 5120
#define ASTG_BYTES (AA_BYTES + 2 * AB_BYTES)   // 20480
#define ATTN_SMEM (3 * ASTG_BYTES)         // 61440
#define N_ITILE (SEQ / 32)                 // 64

__global__ void __launch_bounds__(128, 3)
attn_kernel(float* __restrict__ out) {
    extern __shared__ char smc[];
    const uint32_t sb = smem_u32(smc);
    const int t = threadIdx.x, l = t & 31, w = t >> 5;
    const int wm = w >> 1, wn = w & 1;
    const int b = blockIdx.z, j0 = blockIdx.y * 128, d0 = blockIdx.x * 64;

    const __half* dwb = g_dwh  + (size_t)b * SEQ * SEQ;   // [j][i]
    const __half* kvb = g_kwvh + (size_t)b * DIM * SEQ;   // [d][i]
    const __half* kwb = g_kwh  + (size_t)b * DIM * SEQ;   // [d][i]

    const __half* srcA  = dwb + (size_t)(j0 + t) * SEQ;
    const __half* srcB1 = kvb + (size_t)(d0 + (t >> 1)) * SEQ;
    const __half* srcB2 = kwb + (size_t)(d0 + (t >> 1)) * SEQ;

    float acc1[4][4][4] = {};
    float acc2[4][4][4] = {};

    const uint32_t aRow = wm * 64 + (l & 15);
    const uint32_t aCol = 8 * (l >> 4);
    const uint32_t bRow = wn * 32 + 8 * (l >> 4) + (l & 7);
    const uint32_t bCol = 8 * ((l >> 3) & 1);
    const uint32_t aOff  = (aRow * ASTH + aCol) * 2;
    const uint32_t b1Off = AA_BYTES + (bRow * ASTH + bCol) * 2;
    const uint32_t b2Off = b1Off + AB_BYTES;

    auto load_stage = [&](int tile, int stage) {
        const int i0 = tile * 32;
        const uint32_t s0 = sb + stage * ASTG_BYTES;
        const uint32_t aBase = s0 + t * (ASTH * 2);
        #pragma unroll
        for (int ch = 0; ch < 4; ch++)
            CP_ASYNC16(aBase + ch * 16, srcA + i0 + ch * 8);
        const int bch = 2 * (t & 1);
        const uint32_t b1Base = s0 + AA_BYTES + (t >> 1) * (ASTH * 2);
        const uint32_t b2Base = b1Base + AB_BYTES;
        CP_ASYNC16(b1Base + bch * 16,       srcB1 + i0 + bch * 8);
        CP_ASYNC16(b1Base + (bch + 1) * 16, srcB1 + i0 + (bch + 1) * 8);
        CP_ASYNC16(b2Base + bch * 16,       srcB2 + i0 + bch * 8);
        CP_ASYNC16(b2Base + (bch + 1) * 16, srcB2 + i0 + (bch + 1) * 8);
        CP_COMMIT();
    };

    auto compute_stage = [&](int stage) {
        const uint32_t s0 = sb + stage * ASTG_BYTES;
        #pragma unroll
        for (int ks = 0; ks < 2; ks++) {
            const int kk = ks * 16;
            uint32_t a[4][4], b1[4][2], b2[4][2];
            #pragma unroll
            for (int mt = 0; mt < 4; mt++)
                ldsm_x4(a[mt], s0 + aOff + (mt * 16 * ASTH + kk) * 2);
            #pragma unroll
            for (int np = 0; np < 2; np++) {
                uint32_t r[4];
                ldsm_x4(r, s0 + b1Off + (np * 16 * ASTH + kk) * 2);
                b1[np * 2][0] = r[0]; b1[np * 2][1] = r[1];
                b1[np * 2 + 1][0] = r[2]; b1[np * 2 + 1][1] = r[3];
                ldsm_x4(r, s0 + b2Off + (np * 16 * ASTH + kk) * 2);
                b2[np * 2][0] = r[0]; b2[np * 2][1] = r[1];
                b2[np * 2 + 1][0] = r[2]; b2[np * 2 + 1][1] = r[3];
            }
            #pragma unroll
            for (int mt = 0; mt < 4; mt++) {
                #pragma unroll
                for (int nt = 0; nt < 4; nt++) {
                    mma16(acc1[mt][nt], a[mt], b1[nt]);
                    mma16(acc2[mt][nt], a[mt], b2[nt]);
                }
            }
        }
    };

    load_stage(0, 0);
    load_stage(1, 1);
    for (int tile = 0; tile < N_ITILE; tile++) {
        if (tile == N_ITILE - 1) { CP_WAIT(0); } else { CP_WAIT(1); }
        __syncthreads();
        compute_stage(tile % 3);
        if (tile + 2 < N_ITILE) load_stage(tile + 2, (tile + 2) % 3);
    }

    // epilogue: out = sig * acc1/acc2
    const float* sigb = g_sig + (size_t)b * SEQ * DIM;
    float* outb = out + (size_t)b * SEQ * DIM;
    #pragma unroll
    for (int mt = 0; mt < 4; mt++) {
        #pragma unroll
        for (int nt = 0; nt < 4; nt++) {
            int jr = j0 + wm * 64 + mt * 16 + (l >> 2);
            int dc = d0 + wn * 32 + nt * 8 + 2 * (l & 3);
            size_t i0x = (size_t)jr * DIM + dc;
            size_t i1x = (size_t)(jr + 8) * DIM + dc;
            float2 s0 = *(const float2*)&sigb[i0x];
            float2 s1 = *(const float2*)&sigb[i1x];
            float2 o0, o1;
            o0.x = s0.x * __fdividef(acc1[mt][nt][0], acc2[mt][nt][0]);
            o0.y = s0.y * __fdividef(acc1[mt][nt][1], acc2[mt][nt][1]);
            o1.x = s1.x * __fdividef(acc1[mt][nt][2], acc2[mt][nt][2]);
            o1.y = s1.y * __fdividef(acc1[mt][nt][3], acc2[mt][nt][3]);
            *(float2*)&outb[i0x] = o0;
            *(float2*)&outb[i1x] = o1;
        }
    }
}

// ---------------------------------------------------------------------------
// Launch
// ---------------------------------------------------------------------------
extern "C" void kernel_launch(void* const* d_in, const int* in_sizes, int n_in,
                              void* d_out, int out_size) {
    const float* x     = (const float*)d_in[0];
    const float* dis   = (const float*)d_in[1];
    const float* Wq    = (const float*)d_in[2];
    const float* Wk    = (const float*)d_in[3];
    const float* Wv    = (const float*)d_in[4];
    const float* alpha = (const float*)d_in[5];
    float* out = (float*)d_out;

    cudaFuncSetAttribute(attn_kernel, cudaFuncAttributeMaxDynamicSharedMemorySize, ATTN_SMEM);
    cudaFuncSetAttribute(qkv_kernel,  cudaFuncAttributeMaxDynamicSharedMemorySize, QKV_SMEM);

    {   // weight convert+concat (fp16, [n][k])
        dim3 grid(256, 3), block(256);
        wconv_kernel<<<grid, block>>>(Wq, Wk, Wv);
    }
    {   // x convert
        xh_kernel<<<8192, 256>>>(x);
    }
    {   // dw = fp16(exp(coef*dis)) transposed [b][j][i], vectorized stores
        dim3 grid(SEQ / 32, SEQ / 64, BATCH), block(32, 8);
        dwt_kernel<<<grid, block>>>(dis, alpha);
    }
    {   // fp16 QKV projection (R13 config)
        dim3 grid(NCAT / 128, M_TOT / 128), block(128);
        qkv_kernel<<<grid, block, QKV_SMEM>>>();
    }
    {   // kw / kw*v transpose to fp16 [b][d][i], vectorized stores
        dim3 grid(DIM / 32, SEQ / 64, BATCH), block(32, 8);
        kvt_kernel<<<grid, block>>>();
    }
    {   // fp16 dual-GEMM attention (R13 config)
        dim3 grid(DIM / 64, SEQ / 128, BATCH), block(128);
        attn_kernel<<<grid, block, ATTN_SMEM>>>(out);
    }
}

// round 16
// speedup vs baseline: 1.4029x; 1.2668x over previous
#include <cuda_runtime.h>
#include <cuda_fp16.h>
#include <math.h>
#include <stdint.h>

#define BATCH 8
#define SEQ   2048
#define DIM   512
#define M_TOT (BATCH * SEQ)   // 16384
#define NCAT  (3 * DIM)       // 1536

// Scratch (device globals)
__device__ float  g_sig  [M_TOT * DIM];                 // sigmoid(q) f32 [m][d]
__device__ __half g_xh   [M_TOT * DIM];                 // fp16(x) [m][k]
__device__ __half g_wh   [NCAT * DIM];                  // fp16 W concat [n][k]
__device__ __half g_dwh  [(size_t)BATCH * SEQ * SEQ];   // fp16(exp(coef*dis)) [b][i][j]
__device__ __half g_kwh16[M_TOT * DIM];                 // fp16(exp(k)) [b][i][d]
__device__ __half g_vh16 [M_TOT * DIM];                 // fp16(v)     [b][i][d]
__device__ __half g_kwvh [M_TOT * DIM];                 // fp16(kw*v)  [b][i][d]

// ---------------------------------------------------------------------------
// helpers
// ---------------------------------------------------------------------------
__device__ __forceinline__ uint32_t smem_u32(const void* p) {
    uint32_t a;
    asm("{ .reg .u64 t; cvta.to.shared.u64 t, %1; cvt.u32.u64 %0, t; }" : "=r"(a) : "l"(p));
    return a;
}

#define CP_ASYNC16(dst, src) \
    asm volatile("cp.async.cg.shared.global [%0], [%1], 16;" :: "r"(dst), "l"(src))
#define CP_COMMIT() asm volatile("cp.async.commit_group;" ::: "memory")
#define CP_WAIT(n)  asm volatile("cp.async.wait_group %0;" :: "n"(n) : "memory")

// fp16 m16n8k16
__device__ __forceinline__ void mma16(float* c, const uint32_t* a, const uint32_t* b) {
    asm volatile(
        "mma.sync.aligned.m16n8k16.row.col.f32.f16.f16.f32 "
        "{%0,%1,%2,%3},{%4,%5,%6,%7},{%8,%9},{%0,%1,%2,%3};"
        : "+f"(c[0]), "+f"(c[1]), "+f"(c[2]), "+f"(c[3])
        : "r"(a[0]), "r"(a[1]), "r"(a[2]), "r"(a[3]), "r"(b[0]), "r"(b[1]));
}

__device__ __forceinline__ void ldsm_x4(uint32_t* r, uint32_t addr) {
    asm volatile("ldmatrix.sync.aligned.m8n8.x4.shared.b16 {%0,%1,%2,%3}, [%4];"
        : "=r"(r[0]), "=r"(r[1]), "=r"(r[2]), "=r"(r[3]) : "r"(addr));
}
__device__ __forceinline__ void ldsm_x4t(uint32_t* r, uint32_t addr) {
    asm volatile("ldmatrix.sync.aligned.m8n8.x4.trans.shared.b16 {%0,%1,%2,%3}, [%4];"
        : "=r"(r[0]), "=r"(r[1]), "=r"(r[2]), "=r"(r[3]) : "r"(addr));
}

// ---------------------------------------------------------------------------
// Weight convert+concat: g_wh[z*512 + n][k] = fp16(W_z[n][k])
// ---------------------------------------------------------------------------
__global__ void wconv_kernel(const float* __restrict__ Wq,
                             const float* __restrict__ Wk,
                             const float* __restrict__ Wv) {
    const float* W = (blockIdx.y == 0) ? Wq : (blockIdx.y == 1) ? Wk : Wv;
    int i = (blockIdx.x * 256 + threadIdx.x) * 4;
    float4 v = *(const float4*)&W[i];
    __half* dst = g_wh + (size_t)blockIdx.y * DIM * DIM + i;
    *(__half2*)&dst[0] = __floats2half2_rn(v.x, v.y);
    *(__half2*)&dst[2] = __floats2half2_rn(v.z, v.w);
}

// ---------------------------------------------------------------------------
// x convert: g_xh = fp16(x)
// ---------------------------------------------------------------------------
__global__ void xh_kernel(const float* __restrict__ x) {
    size_t i = ((size_t)blockIdx.x * blockDim.x + threadIdx.x) * 4;
    float4 v = *(const float4*)(x + i);
    *(__half2*)&g_xh[i]     = __floats2half2_rn(v.x, v.y);
    *(__half2*)&g_xh[i + 2] = __floats2half2_rn(v.z, v.w);
}

// ---------------------------------------------------------------------------
// dwe: g_dwh = fp16(exp(coef*dis))  — pure elementwise, natural [i][j] layout
// 8 elems/thread; grid 16384 x 256
// ---------------------------------------------------------------------------
__global__ void dwe_kernel(const float* __restrict__ dis,
                           const float* __restrict__ alpha_p) {
    const float coef = -(alpha_p[0] * 11.0f);   // -alpha*log2(2048)
    size_t i = ((size_t)blockIdx.x * blockDim.x + threadIdx.x) * 8;
    float4 v0 = *(const float4*)(dis + i);
    float4 v1 = *(const float4*)(dis + i + 4);
    __half2 h0 = __floats2half2_rn(__expf(coef * v0.x), __expf(coef * v0.y));
    __half2 h1 = __floats2half2_rn(__expf(coef * v0.z), __expf(coef * v0.w));
    __half2 h2 = __floats2half2_rn(__expf(coef * v1.x), __expf(coef * v1.y));
    __half2 h3 = __floats2half2_rn(__expf(coef * v1.z), __expf(coef * v1.w));
    uint4 o;
    o.x = *(uint32_t*)&h0; o.y = *(uint32_t*)&h1;
    o.z = *(uint32_t*)&h2; o.w = *(uint32_t*)&h3;
    *(uint4*)&g_dwh[i] = o;
}

// ---------------------------------------------------------------------------
// kwv: g_kwvh = g_kwh16 * g_vh16  (fp16 elementwise, 8 elems/thread)
// grid 4096 x 256
// ---------------------------------------------------------------------------
__global__ void kwv_kernel() {
    size_t i = ((size_t)blockIdx.x * blockDim.x + threadIdx.x) * 8;
    uint4 a = *(const uint4*)&g_kwh16[i];
    uint4 b = *(const uint4*)&g_vh16[i];
    uint4 o;
    *(__half2*)&o.x = __hmul2(*(__half2*)&a.x, *(__half2*)&b.x);
    *(__half2*)&o.y = __hmul2(*(__half2*)&a.y, *(__half2*)&b.y);
    *(__half2*)&o.z = __hmul2(*(__half2*)&a.z, *(__half2*)&b.z);
    *(__half2*)&o.w = __hmul2(*(__half2*)&a.w, *(__half2*)&b.w);
    *(uint4*)&g_kwvh[i] = o;
}

// ---------------------------------------------------------------------------
// QKV GEMM (fp16 m16n8k16 + ldmatrix): C[m,n] = sum_k xh[m,k] * wh[n,k]
// BM=128, BN=128, BK=32, 128 thr (4 warps 2x2), warp tile 64x64,
// 3-stage cp.async, 1 sync/tile. grid (12, 128), 3 CTAs/SM.
// Epilogue: q -> sigmoid f32 g_sig; k -> fp16 exp g_kwh16; v -> fp16 g_vh16.
// ---------------------------------------------------------------------------
#define QASTH 40                           // halves per row (32 + 8 pad)
#define QA_BYTES (128 * QASTH * 2)         // 10240
#define QSTG_BYTES (2 * QA_BYTES)          // 20480
#define QKV_SMEM (3 * QSTG_BYTES)          // 61440
#define QN_KTILE (DIM / 32)                // 16

__global__ void __launch_bounds__(128, 3)
qkv_kernel() {
    extern __shared__ char smc[];
    const uint32_t sb = smem_u32(smc);
    const int t = threadIdx.x, l = t & 31, w = t >> 5;
    const int wm = w >> 1, wn = w & 1;
    const int m0 = blockIdx.y * 128, n0 = blockIdx.x * 128;

    float acc[4][8][4] = {};

    const uint32_t aRow = wm * 64 + (l & 15);
    const uint32_t aCol = 8 * (l >> 4);
    const uint32_t bRow = wn * 64 + 8 * (l >> 4) + (l & 7);
    const uint32_t bCol = 8 * ((l >> 3) & 1);
    const uint32_t aOff = (aRow * QASTH + aCol) * 2;
    const uint32_t bOff = QA_BYTES + (bRow * QASTH + bCol) * 2;

    auto load_stage = [&](int kt, int stage) {
        const int k0 = kt * 32;
        const uint32_t s0 = sb + stage * QSTG_BYTES;
        const __half* srcA = g_xh + (size_t)(m0 + t) * DIM + k0;
        const uint32_t aBase = s0 + t * (QASTH * 2);
        #pragma unroll
        for (int ch = 0; ch < 4; ch++)
            CP_ASYNC16(aBase + ch * 16, srcA + ch * 8);
        const __half* srcB = g_wh + (size_t)(n0 + t) * DIM + k0;
        const uint32_t bBase = s0 + QA_BYTES + t * (QASTH * 2);
        #pragma unroll
        for (int ch = 0; ch < 4; ch++)
            CP_ASYNC16(bBase + ch * 16, srcB + ch * 8);
        CP_COMMIT();
    };

    auto compute_stage = [&](int stage) {
        const uint32_t s0 = sb + stage * QSTG_BYTES;
        #pragma unroll
        for (int ks = 0; ks < 2; ks++) {
            const int kk = ks * 16;
            uint32_t a[4][4], b[8][2];
            #pragma unroll
            for (int mt = 0; mt < 4; mt++)
                ldsm_x4(a[mt], s0 + aOff + (mt * 16 * QASTH + kk) * 2);
            #pragma unroll
            for (int np = 0; np < 4; np++) {
                uint32_t r[4];
                ldsm_x4(r, s0 + bOff + (np * 16 * QASTH + kk) * 2);
                b[np * 2][0] = r[0]; b[np * 2][1] = r[1];
                b[np * 2 + 1][0] = r[2]; b[np * 2 + 1][1] = r[3];
            }
            #pragma unroll
            for (int mt = 0; mt < 4; mt++)
                #pragma unroll
                for (int nt = 0; nt < 8; nt++)
                    mma16(acc[mt][nt], a[mt], b[nt]);
        }
    };

    load_stage(0, 0);
    load_stage(1, 1);
    for (int kt = 0; kt < QN_KTILE; kt++) {
        if (kt == QN_KTILE - 1) { CP_WAIT(0); } else { CP_WAIT(1); }
        __syncthreads();
        compute_stage(kt % 3);
        if (kt + 2 < QN_KTILE) load_stage(kt + 2, (kt + 2) % 3);
    }

    const int type = n0 >> 9;   // 0:q 1:k 2:v
    const int nl0 = n0 - type * 512;

    #pragma unroll
    for (int mt = 0; mt < 4; mt++) {
        #pragma unroll
        for (int nt = 0; nt < 8; nt++) {
            int row = m0 + wm * 64 + mt * 16 + (l >> 2);
            int col = nl0 + wn * 64 + nt * 8 + 2 * (l & 3);
            float c0 = acc[mt][nt][0], c1 = acc[mt][nt][1];
            float c2 = acc[mt][nt][2], c3 = acc[mt][nt][3];
            size_t i0x = (size_t)row * DIM + col;
            size_t i1x = (size_t)(row + 8) * DIM + col;
            if (type == 0) {
                g_sig[i0x]     = 1.0f / (1.0f + __expf(-c0));
                g_sig[i0x + 1] = 1.0f / (1.0f + __expf(-c1));
                g_sig[i1x]     = 1.0f / (1.0f + __expf(-c2));
                g_sig[i1x + 1] = 1.0f / (1.0f + __expf(-c3));
            } else if (type == 1) {
                *(__half2*)&g_kwh16[i0x] = __floats2half2_rn(__expf(c0), __expf(c1));
                *(__half2*)&g_kwh16[i1x] = __floats2half2_rn(__expf(c2), __expf(c3));
            } else {
                *(__half2*)&g_vh16[i0x] = __floats2half2_rn(c0, c1);
                *(__half2*)&g_vh16[i1x] = __floats2half2_rn(c2, c3);
            }
        }
    }
}

// ---------------------------------------------------------------------------
// Attention dual-GEMM (fp16 m16n8k16 + ldmatrix.trans, 3-stage, 1 sync/tile)
//   acc1[j,d] += dw[i,j]*kwv[i,d] ; acc2[j,d] += dw[i,j]*kw[i,d]  (contract i)
// Operands stored NATURAL: dw [i][j], kwv/kw [i][d]; fragments via .trans.
// BM=128 (j), BN=64 (d), BK=32 (i); 128 thr (4 warps 2x2), warp tile 64x32
// dual acc. grid (8, 16, 8), 3 CTAs/SM.
// ---------------------------------------------------------------------------
#define AAH 136                            // A row stride in halves (128+8)
#define ABH 72                             // B row stride in halves (64+8)
#define AA_BYTES (32 * AAH * 2)            // 8704
#define AB_BYTES (32 * ABH * 2)            // 4608
#define ASTG_BYTES (AA_BYTES + 2 * AB_BYTES)   // 17920
#define ATTN_SMEM (3 * ASTG_BYTES)         // 53760
#define N_ITILE (SEQ / 32)                 // 64

__global__ void __launch_bounds__(128, 3)
attn_kernel(float* __restrict__ out) {
    extern __shared__ char smc[];
    const uint32_t sb = smem_u32(smc);
    const int t = threadIdx.x, l = t & 31, w = t >> 5;
    const int wm = w >> 1, wn = w & 1;
    const int b = blockIdx.z, j0 = blockIdx.y * 128, d0 = blockIdx.x * 64;

    const __half* dwb = g_dwh  + (size_t)b * SEQ * SEQ;   // [i][j]
    const __half* kvb = g_kwvh + (size_t)b * SEQ * DIM;   // [i][d]
    const __half* kwb = g_kwh16 + (size_t)b * SEQ * DIM;  // [i][d]

    // loaders: thread t -> tile row (t>>2), chunk phase (t&3)
    const int lr = t >> 2, lc = t & 3;
    const __half* srcA  = dwb + (size_t)lr * SEQ + j0;    // + i0*SEQ per tile
    const __half* srcB1 = kvb + (size_t)lr * DIM + d0;
    const __half* srcB2 = kwb + (size_t)lr * DIM + d0;

    float acc1[4][4][4] = {};
    float acc2[4][4][4] = {};

    // trans-ldmatrix lane geometry:
    // A: i = (l&7) + 8*(l>>4), j = 8*((l>>3)&1)   (regs -> a0..a3)
    // B: k = (l&7) + 8*((l>>3)&1), n = 8*(l>>4)   (regs -> b[np2][0],b[np2][1],b[np2+1][0],b[np2+1][1])
    const uint32_t aI = (l & 7) + 8 * (l >> 4);
    const uint32_t aJ = 8 * ((l >> 3) & 1);
    const uint32_t bI = (l & 7) + 8 * ((l >> 3) & 1);
    const uint32_t bN = 8 * (l >> 4);
    const uint32_t aOffL  = (aI * AAH + wm * 64 + aJ) * 2;             // + (mt*16 + kk*AAH)*2
    const uint32_t b1OffL = AA_BYTES + (bI * ABH + wn * 32 + bN) * 2;  // + (np*16 + kk*ABH)*2
    const uint32_t b2OffL = b1OffL + AB_BYTES;

    auto load_stage = [&](int tile, int stage) {
        const size_t i0 = (size_t)tile * 32;
        const uint32_t s0 = sb + stage * ASTG_BYTES;
        // A: 32 rows x 128 j-halves (256B/row); 4 thr/row, 4 chunks each
        const uint32_t aBase = s0 + lr * (AAH * 2);
        #pragma unroll
        for (int it = 0; it < 4; it++) {
            int ch = lc + it * 4;
            CP_ASYNC16(aBase + ch * 16, srcA + i0 * SEQ + ch * 8);
        }
        // B1/B2: 32 rows x 64 d-halves (128B/row); 4 thr/row, 2 chunks each
        const uint32_t b1Base = s0 + AA_BYTES + lr * (ABH * 2);
        const uint32_t b2Base = b1Base + AB_BYTES;
        #pragma unroll
        for (int it = 0; it < 2; it++) {
            int ch = lc + it * 4;
            CP_ASYNC16(b1Base + ch * 16, srcB1 + i0 * DIM + ch * 8);
            CP_ASYNC16(b2Base + ch * 16, srcB2 + i0 * DIM + ch * 8);
        }
        CP_COMMIT();
    };

    auto compute_stage = [&](int stage) {
        const uint32_t s0 = sb + stage * ASTG_BYTES;
        #pragma unroll
        for (int ks = 0; ks < 2; ks++) {
            const int kk = ks * 16;
            uint32_t a[4][4], b1[4][2], b2[4][2];
            #pragma unroll
            for (int mt = 0; mt < 4; mt++)
                ldsm_x4t(a[mt], s0 + aOffL + (kk * AAH + mt * 16) * 2);
            #pragma unroll
            for (int np = 0; np < 2; np++) {
                uint32_t r[4];
                ldsm_x4t(r, s0 + b1OffL + (kk * ABH + np * 16) * 2);
                b1[np * 2][0] = r[0]; b1[np * 2][1] = r[1];
                b1[np * 2 + 1][0] = r[2]; b1[np * 2 + 1][1] = r[3];
                ldsm_x4t(r, s0 + b2OffL + (kk * ABH + np * 16) * 2);
                b2[np * 2][0] = r[0]; b2[np * 2][1] = r[1];
                b2[np * 2 + 1][0] = r[2]; b2[np * 2 + 1][1] = r[3];
            }
            #pragma unroll
            for (int mt = 0; mt < 4; mt++) {
                #pragma unroll
                for (int nt = 0; nt < 4; nt++) {
                    mma16(acc1[mt][nt], a[mt], b1[nt]);
                    mma16(acc2[mt][nt], a[mt], b2[nt]);
                }
            }
        }
    };

    load_stage(0, 0);
    load_stage(1, 1);
    for (int tile = 0; tile < N_ITILE; tile++) {
        if (tile == N_ITILE - 1) { CP_WAIT(0); } else { CP_WAIT(1); }
        __syncthreads();
        compute_stage(tile % 3);
        if (tile + 2 < N_ITILE) load_stage(tile + 2, (tile + 2) % 3);
    }

    // epilogue: out = sig * acc1/acc2
    const float* sigb = g_sig + (size_t)b * SEQ * DIM;
    float* outb = out + (size_t)b * SEQ * DIM;
    #pragma unroll
    for (int mt = 0; mt < 4; mt++) {
        #pragma unroll
        for (int nt = 0; nt < 4; nt++) {
            int jr = j0 + wm * 64 + mt * 16 + (l >> 2);
            int dc = d0 + wn * 32 + nt * 8 + 2 * (l & 3);
            size_t i0x = (size_t)jr * DIM + dc;
            size_t i1x = (size_t)(jr + 8) * DIM + dc;
            float2 s0 = *(const float2*)&sigb[i0x];
            float2 s1 = *(const float2*)&sigb[i1x];
            float2 o0, o1;
            o0.x = s0.x * __fdividef(acc1[mt][nt][0], acc2[mt][nt][0]);
            o0.y = s0.y * __fdividef(acc1[mt][nt][1], acc2[mt][nt][1]);
            o1.x = s1.x * __fdividef(acc1[mt][nt][2], acc2[mt][nt][2]);
            o1.y = s1.y * __fdividef(acc1[mt][nt][3], acc2[mt][nt][3]);
            *(float2*)&outb[i0x] = o0;
            *(float2*)&outb[i1x] = o1;
        }
    }
}

// ---------------------------------------------------------------------------
// Launch
// ---------------------------------------------------------------------------
extern "C" void kernel_launch(void* const* d_in, const int* in_sizes, int n_in,
                              void* d_out, int out_size) {
    const float* x     = (const float*)d_in[0];
    const float* dis   = (const float*)d_in[1];
    const float* Wq    = (const float*)d_in[2];
    const float* Wk    = (const float*)d_in[3];
    const float* Wv    = (const float*)d_in[4];
    const float* alpha = (const float*)d_in[5];
    float* out = (float*)d_out;

    cudaFuncSetAttribute(attn_kernel, cudaFuncAttributeMaxDynamicSharedMemorySize, ATTN_SMEM);
    cudaFuncSetAttribute(qkv_kernel,  cudaFuncAttributeMaxDynamicSharedMemorySize, QKV_SMEM);

    {   // weight convert+concat (fp16, [n][k])
        dim3 grid(256, 3), block(256);
        wconv_kernel<<<grid, block>>>(Wq, Wk, Wv);
    }
    {   // x convert
        xh_kernel<<<8192, 256>>>(x);
    }
    {   // dw = fp16(exp(coef*dis)), natural [i][j] (pure elementwise)
        dwe_kernel<<<16384, 256>>>(dis, alpha);
    }
    {   // fp16 QKV projection; writes sig f32, exp(k) fp16, v fp16
        dim3 grid(NCAT / 128, M_TOT / 128), block(128);
        qkv_kernel<<<grid, block, QKV_SMEM>>>();
    }
    {   // kwv = kw * v (fp16 elementwise)
        kwv_kernel<<<4096, 256>>>();
    }
    {   // fp16 dual-GEMM attention (trans-ldmatrix operands)
        dim3 grid(DIM / 64, SEQ / 128, BATCH), block(128);
        attn_kernel<<<grid, block, ATTN_SMEM>>>(out);
    }
}

// round 17
// speedup vs baseline: 1.4107x; 1.0056x over previous
#include <cuda_runtime.h>
#include <cuda_fp16.h>
#include <math.h>
#include <stdint.h>

#define BATCH 8
#define SEQ   2048
#define DIM   512
#define M_TOT (BATCH * SEQ)   // 16384
#define NCAT  (3 * DIM)       // 1536

// Scratch (device globals)
__device__ __half g_sigh [M_TOT * DIM];                 // fp16 sigmoid(q) [m][d]
__device__ __half g_xh   [M_TOT * DIM];                 // fp16(x) [m][k]
__device__ __half g_wh   [NCAT * DIM];                  // fp16 W concat [n][k], K/V interleaved
__device__ __half g_dwh  [(size_t)BATCH * SEQ * SEQ];   // fp16(exp(coef*dis)) [b][i][j]
__device__ __half g_kwh16[M_TOT * DIM];                 // fp16(exp(k)) [b][i][d]
__device__ __half g_kwvh [M_TOT * DIM];                 // fp16(exp(k)*v) [b][i][d]

// ---------------------------------------------------------------------------
// helpers
// ---------------------------------------------------------------------------
__device__ __forceinline__ uint32_t smem_u32(const void* p) {
    uint32_t a;
    asm("{ .reg .u64 t; cvta.to.shared.u64 t, %1; cvt.u32.u64 %0, t; }" : "=r"(a) : "l"(p));
    return a;
}

#define CP_ASYNC16(dst, src) \
    asm volatile("cp.async.cg.shared.global [%0], [%1], 16;" :: "r"(dst), "l"(src))
#define CP_COMMIT() asm volatile("cp.async.commit_group;" ::: "memory")
#define CP_WAIT(n)  asm volatile("cp.async.wait_group %0;" :: "n"(n) : "memory")

// fp16 m16n8k16
__device__ __forceinline__ void mma16(float* c, const uint32_t* a, const uint32_t* b) {
    asm volatile(
        "mma.sync.aligned.m16n8k16.row.col.f32.f16.f16.f32 "
        "{%0,%1,%2,%3},{%4,%5,%6,%7},{%8,%9},{%0,%1,%2,%3};"
        : "+f"(c[0]), "+f"(c[1]), "+f"(c[2]), "+f"(c[3])
        : "r"(a[0]), "r"(a[1]), "r"(a[2]), "r"(a[3]), "r"(b[0]), "r"(b[1]));
}

__device__ __forceinline__ void ldsm_x4(uint32_t* r, uint32_t addr) {
    asm volatile("ldmatrix.sync.aligned.m8n8.x4.shared.b16 {%0,%1,%2,%3}, [%4];"
        : "=r"(r[0]), "=r"(r[1]), "=r"(r[2]), "=r"(r[3]) : "r"(addr));
}
__device__ __forceinline__ void ldsm_x4t(uint32_t* r, uint32_t addr) {
    asm volatile("ldmatrix.sync.aligned.m8n8.x4.trans.shared.b16 {%0,%1,%2,%3}, [%4];"
        : "=r"(r[0]), "=r"(r[1]), "=r"(r[2]), "=r"(r[3]) : "r"(addr));
}

// ---------------------------------------------------------------------------
// Weight convert+concat, K/V INTERLEAVED in 64-col d-blocks:
//  row n < 512:            Wq row n
//  n >= 512: g=(n-512)>>7, r=(n-512)&127;
//            r<64 -> Wk row g*64+r ; else Wv row g*64+(r-64)
// grid (768, 1), block 256; 4 cols/thread
// ---------------------------------------------------------------------------
__global__ void wconv_kernel(const float* __restrict__ Wq,
                             const float* __restrict__ Wk,
                             const float* __restrict__ Wv) {
    size_t idx = ((size_t)blockIdx.x * 256 + threadIdx.x) * 4;
    int n = (int)(idx >> 9);          // /512
    int col = (int)(idx & 511);
    const float* src;
    if (n < 512) {
        src = Wq + (size_t)n * DIM;
    } else {
        int g = (n - 512) >> 7, r = (n - 512) & 127;
        if (r < 64) src = Wk + (size_t)(g * 64 + r) * DIM;
        else        src = Wv + (size_t)(g * 64 + r - 64) * DIM;
    }
    float4 v = *(const float4*)&src[col];
    __half* dst = g_wh + (size_t)n * DIM + col;
    *(__half2*)&dst[0] = __floats2half2_rn(v.x, v.y);
    *(__half2*)&dst[2] = __floats2half2_rn(v.z, v.w);
}

// ---------------------------------------------------------------------------
// x convert: g_xh = fp16(x)
// ---------------------------------------------------------------------------
__global__ void xh_kernel(const float* __restrict__ x) {
    size_t i = ((size_t)blockIdx.x * blockDim.x + threadIdx.x) * 4;
    float4 v = *(const float4*)(x + i);
    *(__half2*)&g_xh[i]     = __floats2half2_rn(v.x, v.y);
    *(__half2*)&g_xh[i + 2] = __floats2half2_rn(v.z, v.w);
}

// ---------------------------------------------------------------------------
// dwe: g_dwh = fp16(exp(coef*dis)) — elementwise, natural [i][j]; 8/thread
// ---------------------------------------------------------------------------
__global__ void dwe_kernel(const float* __restrict__ dis,
                           const float* __restrict__ alpha_p) {
    const float coef = -(alpha_p[0] * 11.0f);   // -alpha*log2(2048)
    size_t i = ((size_t)blockIdx.x * blockDim.x + threadIdx.x) * 8;
    float4 v0 = *(const float4*)(dis + i);
    float4 v1 = *(const float4*)(dis + i + 4);
    __half2 h0 = __floats2half2_rn(__expf(coef * v0.x), __expf(coef * v0.y));
    __half2 h1 = __floats2half2_rn(__expf(coef * v0.z), __expf(coef * v0.w));
    __half2 h2 = __floats2half2_rn(__expf(coef * v1.x), __expf(coef * v1.y));
    __half2 h3 = __floats2half2_rn(__expf(coef * v1.z), __expf(coef * v1.w));
    uint4 o;
    o.x = *(uint32_t*)&h0; o.y = *(uint32_t*)&h1;
    o.z = *(uint32_t*)&h2; o.w = *(uint32_t*)&h3;
    *(uint4*)&g_dwh[i] = o;
}

// ---------------------------------------------------------------------------
// QKV GEMM (fp16 m16n8k16 + ldmatrix): C[m,n] = sum_k xh[m,k] * wh[n,k]
// BM=128, BN=128, BK=32, 128 thr (4 warps 2x2), warp tile 64x64,
// 3-stage cp.async, 1 sync/tile. grid (12, 128), 3 CTAs/SM.
// Epilogue: n0<512: sigmoid -> g_sigh (fp16).
//           n0>=512: wn=0 warps own kw cols, wn=1 warps own v cols (same d!);
//                    v staged through smem; emit g_kwh16 AND g_kwvh.
// ---------------------------------------------------------------------------
#define QASTH 40                           // halves per row (32 + 8 pad)
#define QA_BYTES (128 * QASTH * 2)         // 10240
#define QSTG_BYTES (2 * QA_BYTES)          // 20480
#define QKV_SMEM (3 * QSTG_BYTES)          // 61440
#define QN_KTILE (DIM / 32)                // 16
#define VBUF_STRIDE 72                     // halves; bank-safe

__global__ void __launch_bounds__(128, 3)
qkv_kernel() {
    extern __shared__ char smc[];
    const uint32_t sb = smem_u32(smc);
    const int t = threadIdx.x, l = t & 31, w = t >> 5;
    const int wm = w >> 1, wn = w & 1;
    const int m0 = blockIdx.y * 128, n0 = blockIdx.x * 128;

    float acc[4][8][4] = {};

    const uint32_t aRow = wm * 64 + (l & 15);
    const uint32_t aCol = 8 * (l >> 4);
    const uint32_t bRow = wn * 64 + 8 * (l >> 4) + (l & 7);
    const uint32_t bCol = 8 * ((l >> 3) & 1);
    const uint32_t aOff = (aRow * QASTH + aCol) * 2;
    const uint32_t bOff = QA_BYTES + (bRow * QASTH + bCol) * 2;

    auto load_stage = [&](int kt, int stage) {
        const int k0 = kt * 32;
        const uint32_t s0 = sb + stage * QSTG_BYTES;
        const __half* srcA = g_xh + (size_t)(m0 + t) * DIM + k0;
        const uint32_t aBase = s0 + t * (QASTH * 2);
        #pragma unroll
        for (int ch = 0; ch < 4; ch++)
            CP_ASYNC16(aBase + ch * 16, srcA + ch * 8);
        const __half* srcB = g_wh + (size_t)(n0 + t) * DIM + k0;
        const uint32_t bBase = s0 + QA_BYTES + t * (QASTH * 2);
        #pragma unroll
        for (int ch = 0; ch < 4; ch++)
            CP_ASYNC16(bBase + ch * 16, srcB + ch * 8);
        CP_COMMIT();
    };

    auto compute_stage = [&](int stage) {
        const uint32_t s0 = sb + stage * QSTG_BYTES;
        #pragma unroll
        for (int ks = 0; ks < 2; ks++) {
            const int kk = ks * 16;
            uint32_t a[4][4], b[8][2];
            #pragma unroll
            for (int mt = 0; mt < 4; mt++)
                ldsm_x4(a[mt], s0 + aOff + (mt * 16 * QASTH + kk) * 2);
            #pragma unroll
            for (int np = 0; np < 4; np++) {
                uint32_t r[4];
                ldsm_x4(r, s0 + bOff + (np * 16 * QASTH + kk) * 2);
                b[np * 2][0] = r[0]; b[np * 2][1] = r[1];
                b[np * 2 + 1][0] = r[2]; b[np * 2 + 1][1] = r[3];
            }
            #pragma unroll
            for (int mt = 0; mt < 4; mt++)
                #pragma unroll
                for (int nt = 0; nt < 8; nt++)
                    mma16(acc[mt][nt], a[mt], b[nt]);
        }
    };

    load_stage(0, 0);
    load_stage(1, 1);
    for (int kt = 0; kt < QN_KTILE; kt++) {
        if (kt == QN_KTILE - 1) { CP_WAIT(0); } else { CP_WAIT(1); }
        __syncthreads();
        compute_stage(kt % 3);
        if (kt + 2 < QN_KTILE) load_stage(kt + 2, (kt + 2) % 3);
    }

    if (n0 < 512) {
        // q -> fp16 sigmoid
        #pragma unroll
        for (int mt = 0; mt < 4; mt++) {
            #pragma unroll
            for (int nt = 0; nt < 8; nt++) {
                int row = m0 + wm * 64 + mt * 16 + (l >> 2);
                int col = n0 + wn * 64 + nt * 8 + 2 * (l & 3);
                float c0 = acc[mt][nt][0], c1 = acc[mt][nt][1];
                float c2 = acc[mt][nt][2], c3 = acc[mt][nt][3];
                c0 = 1.0f / (1.0f + __expf(-c0));
                c1 = 1.0f / (1.0f + __expf(-c1));
                c2 = 1.0f / (1.0f + __expf(-c2));
                c3 = 1.0f / (1.0f + __expf(-c3));
                *(__half2*)&g_sigh[(size_t)row * DIM + col]       = __floats2half2_rn(c0, c1);
                *(__half2*)&g_sigh[(size_t)(row + 8) * DIM + col] = __floats2half2_rn(c2, c3);
            }
        }
    } else {
        // interleaved block: wn=0 cols = kw, wn=1 cols = v, SAME d-range
        const int dbase = ((n0 - 512) >> 7) * 64;
        __half* vbuf = (__half*)smc;     // 128 x VBUF_STRIDE halves (reuse stages)
        __syncthreads();                 // mainloop smem reads done

        if (wn == 1) {                   // stage v into smem
            #pragma unroll
            for (int mt = 0; mt < 4; mt++) {
                #pragma unroll
                for (int nt = 0; nt < 8; nt++) {
                    int r0 = wm * 64 + mt * 16 + (l >> 2);
                    int col = nt * 8 + 2 * (l & 3);
                    *(__half2*)&vbuf[r0 * VBUF_STRIDE + col] =
                        __floats2half2_rn(acc[mt][nt][0], acc[mt][nt][1]);
                    *(__half2*)&vbuf[(r0 + 8) * VBUF_STRIDE + col] =
                        __floats2half2_rn(acc[mt][nt][2], acc[mt][nt][3]);
                }
            }
        }
        __syncthreads();
        if (wn == 0) {                   // emit kw and kw*v
            #pragma unroll
            for (int mt = 0; mt < 4; mt++) {
                #pragma unroll
                for (int nt = 0; nt < 8; nt++) {
                    int r0 = wm * 64 + mt * 16 + (l >> 2);
                    int col = nt * 8 + 2 * (l & 3);
                    float k0 = __expf(acc[mt][nt][0]);
                    float k1 = __expf(acc[mt][nt][1]);
                    float k2 = __expf(acc[mt][nt][2]);
                    float k3 = __expf(acc[mt][nt][3]);
                    __half2 v01 = *(__half2*)&vbuf[r0 * VBUF_STRIDE + col];
                    __half2 v23 = *(__half2*)&vbuf[(r0 + 8) * VBUF_STRIDE + col];
                    size_t i0x = (size_t)(m0 + r0) * DIM + dbase + col;
                    size_t i1x = (size_t)(m0 + r0 + 8) * DIM + dbase + col;
                    *(__half2*)&g_kwh16[i0x] = __floats2half2_rn(k0, k1);
                    *(__half2*)&g_kwh16[i1x] = __floats2half2_rn(k2, k3);
                    *(__half2*)&g_kwvh[i0x] =
                        __floats2half2_rn(k0 * __half2float(v01.x), k1 * __half2float(v01.y));
                    *(__half2*)&g_kwvh[i1x] =
                        __floats2half2_rn(k2 * __half2float(v23.x), k3 * __half2float(v23.y));
                }
            }
        }
    }
}

// ---------------------------------------------------------------------------
// Attention dual-GEMM (fp16 m16n8k16 + ldmatrix.trans, 3-stage, 1 sync/tile)
// Operands stored NATURAL: dw [i][j], kwv/kw [i][d]; fragments via .trans.
// BM=128 (j), BN=64 (d), BK=32 (i); 128 thr (4 warps 2x2), warp tile 64x32
// dual acc. grid (8, 16, 8), 3 CTAs/SM.
// ---------------------------------------------------------------------------
#define AAH 136                            // A row stride in halves (128+8)
#define ABH 72                             // B row stride in halves (64+8)
#define AA_BYTES (32 * AAH * 2)            // 8704
#define AB_BYTES (32 * ABH * 2)            // 4608
#define ASTG_BYTES (AA_BYTES + 2 * AB_BYTES)   // 17920
#define ATTN_SMEM (3 * ASTG_BYTES)         // 53760
#define N_ITILE (SEQ / 32)                 // 64

__global__ void __launch_bounds__(128, 3)
attn_kernel(float* __restrict__ out) {
    extern __shared__ char smc[];
    const uint32_t sb = smem_u32(smc);
    const int t = threadIdx.x, l = t & 31, w = t >> 5;
    const int wm = w >> 1, wn = w & 1;
    const int b = blockIdx.z, j0 = blockIdx.y * 128, d0 = blockIdx.x * 64;

    const __half* dwb = g_dwh  + (size_t)b * SEQ * SEQ;    // [i][j]
    const __half* kvb = g_kwvh + (size_t)b * SEQ * DIM;    // [i][d]
    const __half* kwb = g_kwh16 + (size_t)b * SEQ * DIM;   // [i][d]

    const int lr = t >> 2, lc = t & 3;
    const __half* srcA  = dwb + (size_t)lr * SEQ + j0;
    const __half* srcB1 = kvb + (size_t)lr * DIM + d0;
    const __half* srcB2 = kwb + (size_t)lr * DIM + d0;

    float acc1[4][4][4] = {};
    float acc2[4][4][4] = {};

    const uint32_t aI = (l & 7) + 8 * (l >> 4);
    const uint32_t aJ = 8 * ((l >> 3) & 1);
    const uint32_t bI = (l & 7) + 8 * ((l >> 3) & 1);
    const uint32_t bN = 8 * (l >> 4);
    const uint32_t aOffL  = (aI * AAH + wm * 64 + aJ) * 2;
    const uint32_t b1OffL = AA_BYTES + (bI * ABH + wn * 32 + bN) * 2;
    const uint32_t b2OffL = b1OffL + AB_BYTES;

    auto load_stage = [&](int tile, int stage) {
        const size_t i0 = (size_t)tile * 32;
        const uint32_t s0 = sb + stage * ASTG_BYTES;
        const uint32_t aBase = s0 + lr * (AAH * 2);
        #pragma unroll
        for (int it = 0; it < 4; it++) {
            int ch = lc + it * 4;
            CP_ASYNC16(aBase + ch * 16, srcA + i0 * SEQ + ch * 8);
        }
        const uint32_t b1Base = s0 + AA_BYTES + lr * (ABH * 2);
        const uint32_t b2Base = b1Base + AB_BYTES;
        #pragma unroll
        for (int it = 0; it < 2; it++) {
            int ch = lc + it * 4;
            CP_ASYNC16(b1Base + ch * 16, srcB1 + i0 * DIM + ch * 8);
            CP_ASYNC16(b2Base + ch * 16, srcB2 + i0 * DIM + ch * 8);
        }
        CP_COMMIT();
    };

    auto compute_stage = [&](int stage) {
        const uint32_t s0 = sb + stage * ASTG_BYTES;
        #pragma unroll
        for (int ks = 0; ks < 2; ks++) {
            const int kk = ks * 16;
            uint32_t a[4][4], b1[4][2], b2[4][2];
            #pragma unroll
            for (int mt = 0; mt < 4; mt++)
                ldsm_x4t(a[mt], s0 + aOffL + (kk * AAH + mt * 16) * 2);
            #pragma unroll
            for (int np = 0; np < 2; np++) {
                uint32_t r[4];
                ldsm_x4t(r, s0 + b1OffL + (kk * ABH + np * 16) * 2);
                b1[np * 2][0] = r[0]; b1[np * 2][1] = r[1];
                b1[np * 2 + 1][0] = r[2]; b1[np * 2 + 1][1] = r[3];
                ldsm_x4t(r, s0 + b2OffL + (kk * ABH + np * 16) * 2);
                b2[np * 2][0] = r[0]; b2[np * 2][1] = r[1];
                b2[np * 2 + 1][0] = r[2]; b2[np * 2 + 1][1] = r[3];
            }
            #pragma unroll
            for (int mt = 0; mt < 4; mt++) {
                #pragma unroll
                for (int nt = 0; nt < 4; nt++) {
                    mma16(acc1[mt][nt], a[mt], b1[nt]);
                    mma16(acc2[mt][nt], a[mt], b2[nt]);
                }
            }
        }
    };

    load_stage(0, 0);
    load_stage(1, 1);
    for (int tile = 0; tile < N_ITILE; tile++) {
        if (tile == N_ITILE - 1) { CP_WAIT(0); } else { CP_WAIT(1); }
        __syncthreads();
        compute_stage(tile % 3);
        if (tile + 2 < N_ITILE) load_stage(tile + 2, (tile + 2) % 3);
    }

    // epilogue: out = sig * acc1/acc2  (sig is fp16 now)
    const __half* sigb = g_sigh + (size_t)b * SEQ * DIM;
    float* outb = out + (size_t)b * SEQ * DIM;
    #pragma unroll
    for (int mt = 0; mt < 4; mt++) {
        #pragma unroll
        for (int nt = 0; nt < 4; nt++) {
            int jr = j0 + wm * 64 + mt * 16 + (l >> 2);
            int dc = d0 + wn * 32 + nt * 8 + 2 * (l & 3);
            size_t i0x = (size_t)jr * DIM + dc;
            size_t i1x = (size_t)(jr + 8) * DIM + dc;
            __half2 s0h = *(const __half2*)&sigb[i0x];
            __half2 s1h = *(const __half2*)&sigb[i1x];
            float2 o0, o1;
            o0.x = __half2float(s0h.x) * __fdividef(acc1[mt][nt][0], acc2[mt][nt][0]);
            o0.y = __half2float(s0h.y) * __fdividef(acc1[mt][nt][1], acc2[mt][nt][1]);
            o1.x = __half2float(s1h.x) * __fdividef(acc1[mt][nt][2], acc2[mt][nt][2]);
            o1.y = __half2float(s1h.y) * __fdividef(acc1[mt][nt][3], acc2[mt][nt][3]);
            *(float2*)&outb[i0x] = o0;
            *(float2*)&outb[i1x] = o1;
        }
    }
}

// ---------------------------------------------------------------------------
// Launch
// ---------------------------------------------------------------------------
extern "C" void kernel_launch(void* const* d_in, const int* in_sizes, int n_in,
                              void* d_out, int out_size) {
    const float* x     = (const float*)d_in[0];
    const float* dis   = (const float*)d_in[1];
    const float* Wq    = (const float*)d_in[2];
    const float* Wk    = (const float*)d_in[3];
    const float* Wv    = (const float*)d_in[4];
    const float* alpha = (const float*)d_in[5];
    float* out = (float*)d_out;

    cudaFuncSetAttribute(attn_kernel, cudaFuncAttributeMaxDynamicSharedMemorySize, ATTN_SMEM);
    cudaFuncSetAttribute(qkv_kernel,  cudaFuncAttributeMaxDynamicSharedMemorySize, QKV_SMEM);

    {   // weight convert, K/V interleaved concat
        wconv_kernel<<<768, 256>>>(Wq, Wk, Wv);
    }
    {   // x convert
        xh_kernel<<<8192, 256>>>(x);
    }
    {   // dw = fp16(exp(coef*dis)), natural [i][j]
        dwe_kernel<<<16384, 256>>>(dis, alpha);
    }
    {   // fp16 QKV projection; emits sig fp16, kw fp16, kw*v fp16 (fused)
        dim3 grid(NCAT / 128, M_TOT / 128), block(128);
        qkv_kernel<<<grid, block, QKV_SMEM>>>();
    }
    {   // fp16 dual-GEMM attention
        dim3 grid(DIM / 64, SEQ / 128, BATCH), block(128);
        attn_kernel<<<grid, block, ATTN_SMEM>>>(out);
    }
}